// round 15
// baseline (speedup 1.0000x reference)
#include <cuda_runtime.h>
#include <float.h>

#define BN 512
#define DN 256
#define NT 16            // 512 / 32 tiles per dim
#define NBLK 136         // NT*(NT+1)/2 upper-triangular tiles
#define MBLK 128         // mine kernel CTAs (4 warps = 4 anchors each)

// Scratch (no allocations allowed)
__device__ float g_pd[BN * BN];
__device__ float g_ploss[BN];
__device__ int   g_pcnt[BN];
__device__ unsigned int g_done;    // reset by last CTA each call

// ---------------------------------------------------------------------------
// Kernel A (R11-exact): symmetric pairwise sq-distance GEMM, norms fused into
// tile loads, global-load prefetch. 136 CTAs x 256 threads, split-K x4.
// ---------------------------------------------------------------------------
__global__ void __launch_bounds__(256) pd_fused(const float* __restrict__ emb) {
    __shared__ float As[4][32][32];   // reused as partial-sum scratch after loop
    __shared__ float Bs[4][32][32];
    __shared__ float nA[4][32], nB[4][32];
    __shared__ float sqA[32], sqB[32];

    const int tid = threadIdx.x;

    // decode linear block -> (ti, tj), ti <= tj
    int b = blockIdx.x, ti = 0;
    while (b >= NT - ti) { b -= NT - ti; ti++; }
    const int tj = ti + b;
    const int i0 = ti * 32, j0 = tj * 32;

    const int t    = tid & 63;
    const int g    = tid >> 6;             // 0..3, k in [g*64, g*64+64)
    const int lr   = t >> 1;               // load row 0..31
    const int half = t & 1;                // k-half within 32-chunk
    const int ty   = t >> 3;               // 0..7 -> 4 i-rows
    const int tx   = t & 7;                // 0..7 -> 4 j-cols

    float acc[4][4] = {};
    float na = 0.f, nb = 0.f;              // norm partials

    {
        const float* Arow = emb + (i0 + lr) * DN + g * 64;
        const float* Brow = emb + (j0 + lr) * DN + g * 64;

        // prefetch chunk 0 into registers
        float4 pa[4], pb[4];
        #pragma unroll
        for (int e = 0; e < 4; e++) {
            const int ko = half * 16 + e * 4;
            pa[e] = *(const float4*)(Arow + ko);
            pb[e] = *(const float4*)(Brow + ko);
        }

        #pragma unroll
        for (int c0 = 0; c0 < 64; c0 += 32) {
            __syncthreads();
            #pragma unroll
            for (int e = 0; e < 4; e++) {
                const int ko = half * 16 + e * 4;
                const float4 a4 = pa[e];
                const float4 b4 = pb[e];
                na = fmaf(a4.x, a4.x, fmaf(a4.y, a4.y, fmaf(a4.z, a4.z, fmaf(a4.w, a4.w, na))));
                nb = fmaf(b4.x, b4.x, fmaf(b4.y, b4.y, fmaf(b4.z, b4.z, fmaf(b4.w, b4.w, nb))));
                As[g][ko + 0][lr] = a4.x; As[g][ko + 1][lr] = a4.y;
                As[g][ko + 2][lr] = a4.z; As[g][ko + 3][lr] = a4.w;
                Bs[g][ko + 0][lr] = b4.x; Bs[g][ko + 1][lr] = b4.y;
                Bs[g][ko + 2][lr] = b4.z; Bs[g][ko + 3][lr] = b4.w;
            }
            __syncthreads();
            // prefetch next chunk (issues before FMA block, hidden under it)
            if (c0 == 0) {
                #pragma unroll
                for (int e = 0; e < 4; e++) {
                    const int ko = half * 16 + e * 4;
                    pa[e] = *(const float4*)(Arow + 32 + ko);
                    pb[e] = *(const float4*)(Brow + 32 + ko);
                }
            }
            #pragma unroll
            for (int kk = 0; kk < 32; kk++) {
                float4 av = *(const float4*)&As[g][kk][ty << 2];
                float4 bv = *(const float4*)&Bs[g][kk][tx << 2];
                float ar[4] = {av.x, av.y, av.z, av.w};
                float br[4] = {bv.x, bv.y, bv.z, bv.w};
                #pragma unroll
                for (int u = 0; u < 4; u++)
                    #pragma unroll
                    for (int v = 0; v < 4; v++)
                        acc[u][v] = fmaf(ar[u], br[v], acc[u][v]);
            }
        }
    }

    // ---- norm combine: lanes (2m, 2m+1) share row lr ----
    na += __shfl_xor_sync(0xffffffffu, na, 1);
    nb += __shfl_xor_sync(0xffffffffu, nb, 1);
    if (!half) { nA[g][lr] = na; nB[g][lr] = nb; }
    __syncthreads();
    if (g == 0) {
        if (t < 32) sqA[t] = (nA[0][t] + nA[1][t]) + (nA[2][t] + nA[3][t]);
        else        sqB[t - 32] = (nB[0][t - 32] + nB[1][t - 32]) + (nB[2][t - 32] + nB[3][t - 32]);
    }
    // groups 1..3 park their partials in As-scratch (disjoint from sqA/sqB)
    if (g > 0) {
        float* dst = &As[0][0][0] + ((g - 1) * 64 + t) * 16;
        #pragma unroll
        for (int u = 0; u < 4; u++)
            #pragma unroll
            for (int v = 0; v < 4; v++) dst[u * 4 + v] = acc[u][v];
    }
    __syncthreads();

    if (g == 0) {
        const float* p1 = &As[0][0][0] + (0 * 64 + t) * 16;
        const float* p2 = &As[0][0][0] + (1 * 64 + t) * 16;
        const float* p3 = &As[0][0][0] + (2 * 64 + t) * 16;
        float d[4][4];
        #pragma unroll
        for (int u = 0; u < 4; u++) {
            const int gi = i0 + (ty << 2) + u;
            const float sqi = sqA[(ty << 2) + u];
            #pragma unroll
            for (int v = 0; v < 4; v++) {
                const int gj = j0 + (tx << 2) + v;
                const int e = u * 4 + v;
                const float dot = (acc[u][v] + p1[e]) + (p2[e] + p3[e]);
                float val = fmaxf(sqi + sqB[(tx << 2) + v] - 2.f * dot, 0.f);
                if (gi == gj) val = 0.f;
                d[u][v] = val;
            }
            *(float4*)(g_pd + gi * BN + j0 + (tx << 2)) =
                make_float4(d[u][0], d[u][1], d[u][2], d[u][3]);
        }
        if (ti != tj) {
            #pragma unroll
            for (int v = 0; v < 4; v++) {
                const int gj = j0 + (tx << 2) + v;
                *(float2*)(g_pd + gj * BN + i0 + (ty << 2)) =
                    make_float2(d[0][v], d[1][v]);
                *(float2*)(g_pd + gj * BN + i0 + (ty << 2) + 2) =
                    make_float2(d[2][v], d[3][v]);
            }
        }
    }
}

// ---------------------------------------------------------------------------
// Kernel B (R11 + row-load hoist): warp-per-anchor semi-hard mining + fused
// final reduction. 128 CTAs x 128 threads; warp w of CTA cb owns anchor
// j = cb*4 + w. Row LDGs issued BEFORE label staging so their L2 latency
// overlaps the label stage + sync. Layout: v[c] = row[c*32 + lane].
// ---------------------------------------------------------------------------
__global__ void __launch_bounds__(128) mine_final(const int* __restrict__ labels,
                                                  float* __restrict__ out) {
    const int tid = threadIdx.x;
    const int lane = tid & 31, w = tid >> 5;
    const unsigned FULL = 0xffffffffu;

    __shared__ int   s_lab[BN];
    __shared__ float s_row[4][BN];
    __shared__ int s_last;

    const int j = blockIdx.x * 4 + w;          // anchor (0..511)
    const float* rowp = g_pd + j * BN;

    // issue row loads first (independent of labels; overlaps stage+sync)
    float v[16];
    #pragma unroll
    for (int c = 0; c < 16; c++) {
        v[c] = rowp[c * 32 + lane];
    }

    // stage labels
    #pragma unroll
    for (int k = tid; k < BN; k += 128) s_lab[k] = labels[k];
    __syncthreads();

    const int lj = s_lab[j];

    // build masks + stash row in smem for t-broadcast
    unsigned nmask = 0, pmask = 0;
    #pragma unroll
    for (int c = 0; c < 16; c++) {
        const int k = c * 32 + lane;
        s_row[w][k] = v[c];
        const bool same = (s_lab[k] == lj);
        if (!same) nmask |= (1u << c);
        if (same && k != j) pmask |= (1u << c);
    }

    // neg_inside: max over negatives (fallback: min over full row)
    float mx = -FLT_MAX, mn = FLT_MAX;
    #pragma unroll
    for (int c = 0; c < 16; c++) {
        if ((nmask >> c) & 1) mx = fmaxf(mx, v[c]);
        mn = fminf(mn, v[c]);
    }
    #pragma unroll
    for (int o = 16; o; o >>= 1) {
        mx = fmaxf(mx, __shfl_xor_sync(FULL, mx, o));
        mn = fminf(mn, __shfl_xor_sync(FULL, mn, o));
    }
    const float ninside = (mx > -FLT_MAX) ? mx : mn;

    // iterate positives deterministically, process in pairs (overlap shfl chains)
    float wsum = 0.f;
    int cnt = 0;
    int pend = -1;
    #pragma unroll 1
    for (int c = 0; c < 16; c++) {
        unsigned pm = __ballot_sync(FULL, (pmask >> c) & 1);
        while (pm) {
            const int bb = __ffs(pm) - 1;
            pm &= pm - 1;
            const int i = c * 32 + bb;
            cnt++;
            if (pend < 0) { pend = i; continue; }
            const float t1 = s_row[w][pend];
            const float t2 = s_row[w][i];
            float m1 = FLT_MAX, m2 = FLT_MAX;
            #pragma unroll
            for (int cc = 0; cc < 16; cc++) {
                if ((nmask >> cc) & 1) {
                    const float x = v[cc];
                    if (x > t1) m1 = fminf(m1, x);
                    if (x > t2) m2 = fminf(m2, x);
                }
            }
            #pragma unroll
            for (int o = 16; o; o >>= 1) {
                m1 = fminf(m1, __shfl_xor_sync(FULL, m1, o));
                m2 = fminf(m2, __shfl_xor_sync(FULL, m2, o));
            }
            const float semi1 = (m1 < FLT_MAX) ? m1 : ninside;
            const float semi2 = (m2 < FLT_MAX) ? m2 : ninside;
            wsum += fmaxf(1.0f + t1 - semi1, 0.f);
            wsum += fmaxf(1.0f + t2 - semi2, 0.f);
            pend = -1;
        }
    }
    if (pend >= 0) {
        const float t1 = s_row[w][pend];
        float m1 = FLT_MAX;
        #pragma unroll
        for (int cc = 0; cc < 16; cc++) {
            if ((nmask >> cc) & 1) {
                const float x = v[cc];
                if (x > t1) m1 = fminf(m1, x);
            }
        }
        #pragma unroll
        for (int o = 16; o; o >>= 1)
            m1 = fminf(m1, __shfl_xor_sync(FULL, m1, o));
        const float semi1 = (m1 < FLT_MAX) ? m1 : ninside;
        wsum += fmaxf(1.0f + t1 - semi1, 0.f);
    }

    if (lane == 0) {
        g_ploss[j] = wsum;
        g_pcnt[j]  = cnt;
    }
    __syncthreads();
    if (tid == 0) {
        __threadfence();
        const unsigned int vd = atomicAdd(&g_done, 1u);
        s_last = (vd == (unsigned)(gridDim.x - 1)) ? 1 : 0;
    }
    __syncthreads();

    // last CTA: deterministic final reduction over fixed-order arrays
    if (s_last) {
        __threadfence();  // acquire
        float s = 0.f, c = 0.f;
        #pragma unroll
        for (int r = 0; r < 4; r++) {
            s += g_ploss[tid + r * 128];
            c += (float)g_pcnt[tid + r * 128];
        }
        #pragma unroll
        for (int o = 16; o; o >>= 1) {
            s += __shfl_xor_sync(FULL, s, o);
            c += __shfl_xor_sync(FULL, c, o);
        }
        __shared__ float ss[4], cc2[4];
        if (lane == 0) { ss[w] = s; cc2[w] = c; }
        __syncthreads();
        if (tid == 0) {
            float ts = 0.f, tc = 0.f;
            #pragma unroll
            for (int i = 0; i < 4; i++) { ts += ss[i]; tc += cc2[i]; }
            out[0] = ts / tc;
            g_done = 0;   // reset for next graph replay
        }
    }
}

// ---------------------------------------------------------------------------
extern "C" void kernel_launch(void* const* d_in, const int* in_sizes, int n_in,
                              void* d_out, int out_size) {
    const float* emb = (const float*)d_in[0];
    const int* labels = (const int*)d_in[1];
    float* out = (float*)d_out;

    pd_fused<<<NBLK, 256>>>(emb);
    mine_final<<<MBLK, 128>>>(labels, out);
}

// round 17
// speedup vs baseline: 1.0152x; 1.0152x over previous
#include <cuda_runtime.h>
#include <float.h>

#define BN 512
#define DN 256
#define NT 16            // 512 / 32 tiles per dim
#define NBLK 136         // NT*(NT+1)/2 upper-triangular tiles
#define MBLK 128         // mine kernel CTAs (4 warps = 4 anchors each)

// Scratch (no allocations allowed)
__device__ float g_pd[BN * BN];
__device__ float g_ploss[BN];
__device__ int   g_pcnt[BN];
__device__ unsigned int g_done;    // reset by last CTA each call

// ---------------------------------------------------------------------------
// Kernel A (R11-exact): symmetric pairwise sq-distance GEMM, norms fused into
// tile loads, global-load prefetch. 136 CTAs x 256 threads, split-K x4.
// ---------------------------------------------------------------------------
__global__ void __launch_bounds__(256) pd_fused(const float* __restrict__ emb) {
    __shared__ float As[4][32][32];   // reused as partial-sum scratch after loop
    __shared__ float Bs[4][32][32];
    __shared__ float nA[4][32], nB[4][32];
    __shared__ float sqA[32], sqB[32];

    const int tid = threadIdx.x;

    // decode linear block -> (ti, tj), ti <= tj
    int b = blockIdx.x, ti = 0;
    while (b >= NT - ti) { b -= NT - ti; ti++; }
    const int tj = ti + b;
    const int i0 = ti * 32, j0 = tj * 32;

    const int t    = tid & 63;
    const int g    = tid >> 6;             // 0..3, k in [g*64, g*64+64)
    const int lr   = t >> 1;               // load row 0..31
    const int half = t & 1;                // k-half within 32-chunk
    const int ty   = t >> 3;               // 0..7 -> 4 i-rows
    const int tx   = t & 7;                // 0..7 -> 4 j-cols

    float acc[4][4] = {};
    float na = 0.f, nb = 0.f;              // norm partials

    {
        const float* Arow = emb + (i0 + lr) * DN + g * 64;
        const float* Brow = emb + (j0 + lr) * DN + g * 64;

        // prefetch chunk 0 into registers
        float4 pa[4], pb[4];
        #pragma unroll
        for (int e = 0; e < 4; e++) {
            const int ko = half * 16 + e * 4;
            pa[e] = *(const float4*)(Arow + ko);
            pb[e] = *(const float4*)(Brow + ko);
        }

        #pragma unroll
        for (int c0 = 0; c0 < 64; c0 += 32) {
            __syncthreads();
            #pragma unroll
            for (int e = 0; e < 4; e++) {
                const int ko = half * 16 + e * 4;
                const float4 a4 = pa[e];
                const float4 b4 = pb[e];
                na = fmaf(a4.x, a4.x, fmaf(a4.y, a4.y, fmaf(a4.z, a4.z, fmaf(a4.w, a4.w, na))));
                nb = fmaf(b4.x, b4.x, fmaf(b4.y, b4.y, fmaf(b4.z, b4.z, fmaf(b4.w, b4.w, nb))));
                As[g][ko + 0][lr] = a4.x; As[g][ko + 1][lr] = a4.y;
                As[g][ko + 2][lr] = a4.z; As[g][ko + 3][lr] = a4.w;
                Bs[g][ko + 0][lr] = b4.x; Bs[g][ko + 1][lr] = b4.y;
                Bs[g][ko + 2][lr] = b4.z; Bs[g][ko + 3][lr] = b4.w;
            }
            __syncthreads();
            // prefetch next chunk (issues before FMA block, hidden under it)
            if (c0 == 0) {
                #pragma unroll
                for (int e = 0; e < 4; e++) {
                    const int ko = half * 16 + e * 4;
                    pa[e] = *(const float4*)(Arow + 32 + ko);
                    pb[e] = *(const float4*)(Brow + 32 + ko);
                }
            }
            #pragma unroll
            for (int kk = 0; kk < 32; kk++) {
                float4 av = *(const float4*)&As[g][kk][ty << 2];
                float4 bv = *(const float4*)&Bs[g][kk][tx << 2];
                float ar[4] = {av.x, av.y, av.z, av.w};
                float br[4] = {bv.x, bv.y, bv.z, bv.w};
                #pragma unroll
                for (int u = 0; u < 4; u++)
                    #pragma unroll
                    for (int v = 0; v < 4; v++)
                        acc[u][v] = fmaf(ar[u], br[v], acc[u][v]);
            }
        }
    }

    // ---- norm combine: lanes (2m, 2m+1) share row lr ----
    na += __shfl_xor_sync(0xffffffffu, na, 1);
    nb += __shfl_xor_sync(0xffffffffu, nb, 1);
    if (!half) { nA[g][lr] = na; nB[g][lr] = nb; }
    __syncthreads();
    if (g == 0) {
        if (t < 32) sqA[t] = (nA[0][t] + nA[1][t]) + (nA[2][t] + nA[3][t]);
        else        sqB[t - 32] = (nB[0][t - 32] + nB[1][t - 32]) + (nB[2][t - 32] + nB[3][t - 32]);
    }
    // groups 1..3 park their partials in As-scratch (disjoint from sqA/sqB)
    if (g > 0) {
        float* dst = &As[0][0][0] + ((g - 1) * 64 + t) * 16;
        #pragma unroll
        for (int u = 0; u < 4; u++)
            #pragma unroll
            for (int v = 0; v < 4; v++) dst[u * 4 + v] = acc[u][v];
    }
    __syncthreads();

    if (g == 0) {
        const float* p1 = &As[0][0][0] + (0 * 64 + t) * 16;
        const float* p2 = &As[0][0][0] + (1 * 64 + t) * 16;
        const float* p3 = &As[0][0][0] + (2 * 64 + t) * 16;
        float d[4][4];
        #pragma unroll
        for (int u = 0; u < 4; u++) {
            const int gi = i0 + (ty << 2) + u;
            const float sqi = sqA[(ty << 2) + u];
            #pragma unroll
            for (int v = 0; v < 4; v++) {
                const int gj = j0 + (tx << 2) + v;
                const int e = u * 4 + v;
                const float dot = (acc[u][v] + p1[e]) + (p2[e] + p3[e]);
                float val = fmaxf(sqi + sqB[(tx << 2) + v] - 2.f * dot, 0.f);
                if (gi == gj) val = 0.f;
                d[u][v] = val;
            }
            *(float4*)(g_pd + gi * BN + j0 + (tx << 2)) =
                make_float4(d[u][0], d[u][1], d[u][2], d[u][3]);
        }
        if (ti != tj) {
            #pragma unroll
            for (int v = 0; v < 4; v++) {
                const int gj = j0 + (tx << 2) + v;
                *(float2*)(g_pd + gj * BN + i0 + (ty << 2)) =
                    make_float2(d[0][v], d[1][v]);
                *(float2*)(g_pd + gj * BN + i0 + (ty << 2) + 2) =
                    make_float2(d[2][v], d[3][v]);
            }
        }
    }
}

// ---------------------------------------------------------------------------
// Kernel B (R11 mine + hoisted LDG.128 row loads): warp-per-anchor semi-hard
// mining + fused final reduction. 128 CTAs x 128 threads; warp w of CTA cb
// owns anchor j = cb*4 + w. Row loaded as 4x LDG.128 BEFORE label staging so
// L2 latency overlaps the stage+sync. Labels staged in smem (shared by CTA).
// Row register layout: v[c*4+e] = row[c*128 + lane*4 + e].
// ---------------------------------------------------------------------------
__global__ void __launch_bounds__(128) mine_final(const int* __restrict__ labels,
                                                  float* __restrict__ out) {
    const int tid = threadIdx.x;
    const int lane = tid & 31, w = tid >> 5;
    const unsigned FULL = 0xffffffffu;

    __shared__ int   s_lab[BN];
    __shared__ float s_row[4][BN];
    __shared__ int s_last;

    const int j = blockIdx.x * 4 + w;          // anchor (0..511)
    const float* rowp = g_pd + j * BN;

    // issue wide row loads first (independent of labels; overlap stage+sync)
    float4 r4[4];
    #pragma unroll
    for (int c = 0; c < 4; c++) {
        r4[c] = *(const float4*)(rowp + c * 128 + lane * 4);
    }

    // stage labels
    #pragma unroll
    for (int k = tid; k < BN; k += 128) s_lab[k] = labels[k];
    __syncthreads();

    const int lj = s_lab[j];

    // unpack row, stash in smem for t-broadcast, build masks
    float v[16];
    unsigned nmask = 0, pmask = 0;
    #pragma unroll
    for (int c = 0; c < 4; c++) {
        const int kb = c * 128 + lane * 4;
        v[c * 4 + 0] = r4[c].x; v[c * 4 + 1] = r4[c].y;
        v[c * 4 + 2] = r4[c].z; v[c * 4 + 3] = r4[c].w;
        *(float4*)&s_row[w][kb] = r4[c];
        #pragma unroll
        for (int e = 0; e < 4; e++) {
            const int k = kb + e;
            const bool same = (s_lab[k] == lj);
            if (!same) nmask |= (1u << (c * 4 + e));
            if (same && k != j) pmask |= (1u << (c * 4 + e));
        }
    }

    // neg_inside: max over negatives (fallback: min over full row)
    float mx = -FLT_MAX, mn = FLT_MAX;
    #pragma unroll
    for (int c = 0; c < 16; c++) {
        if ((nmask >> c) & 1) mx = fmaxf(mx, v[c]);
        mn = fminf(mn, v[c]);
    }
    #pragma unroll
    for (int o = 16; o; o >>= 1) {
        mx = fmaxf(mx, __shfl_xor_sync(FULL, mx, o));
        mn = fminf(mn, __shfl_xor_sync(FULL, mn, o));
    }
    const float ninside = (mx > -FLT_MAX) ? mx : mn;

    // iterate positives deterministically, process in pairs (overlap shfl chains)
    float wsum = 0.f;
    int cnt = 0;
    int pend = -1;
    #pragma unroll 1
    for (int ce = 0; ce < 16; ce++) {
        unsigned pm = __ballot_sync(FULL, (pmask >> ce) & 1);
        while (pm) {
            const int bb = __ffs(pm) - 1;
            pm &= pm - 1;
            const int i = (ce >> 2) * 128 + bb * 4 + (ce & 3);
            cnt++;
            if (pend < 0) { pend = i; continue; }
            const float t1 = s_row[w][pend];
            const float t2 = s_row[w][i];
            float m1 = FLT_MAX, m2 = FLT_MAX;
            #pragma unroll
            for (int cc = 0; cc < 16; cc++) {
                if ((nmask >> cc) & 1) {
                    const float x = v[cc];
                    if (x > t1) m1 = fminf(m1, x);
                    if (x > t2) m2 = fminf(m2, x);
                }
            }
            #pragma unroll
            for (int o = 16; o; o >>= 1) {
                m1 = fminf(m1, __shfl_xor_sync(FULL, m1, o));
                m2 = fminf(m2, __shfl_xor_sync(FULL, m2, o));
            }
            const float semi1 = (m1 < FLT_MAX) ? m1 : ninside;
            const float semi2 = (m2 < FLT_MAX) ? m2 : ninside;
            wsum += fmaxf(1.0f + t1 - semi1, 0.f);
            wsum += fmaxf(1.0f + t2 - semi2, 0.f);
            pend = -1;
        }
    }
    if (pend >= 0) {
        const float t1 = s_row[w][pend];
        float m1 = FLT_MAX;
        #pragma unroll
        for (int cc = 0; cc < 16; cc++) {
            if ((nmask >> cc) & 1) {
                const float x = v[cc];
                if (x > t1) m1 = fminf(m1, x);
            }
        }
        #pragma unroll
        for (int o = 16; o; o >>= 1)
            m1 = fminf(m1, __shfl_xor_sync(FULL, m1, o));
        const float semi1 = (m1 < FLT_MAX) ? m1 : ninside;
        wsum += fmaxf(1.0f + t1 - semi1, 0.f);
    }

    if (lane == 0) {
        g_ploss[j] = wsum;
        g_pcnt[j]  = cnt;
    }
    __syncthreads();
    if (tid == 0) {
        __threadfence();
        const unsigned int vd = atomicAdd(&g_done, 1u);
        s_last = (vd == (unsigned)(gridDim.x - 1)) ? 1 : 0;
    }
    __syncthreads();

    // last CTA: deterministic final reduction over fixed-order arrays
    if (s_last) {
        __threadfence();  // acquire
        float s = 0.f, c = 0.f;
        #pragma unroll
        for (int r = 0; r < 4; r++) {
            s += g_ploss[tid + r * 128];
            c += (float)g_pcnt[tid + r * 128];
        }
        #pragma unroll
        for (int o = 16; o; o >>= 1) {
            s += __shfl_xor_sync(FULL, s, o);
            c += __shfl_xor_sync(FULL, c, o);
        }
        __shared__ float ss[4], cc2[4];
        if (lane == 0) { ss[w] = s; cc2[w] = c; }
        __syncthreads();
        if (tid == 0) {
            float ts = 0.f, tc = 0.f;
            #pragma unroll
            for (int i = 0; i < 4; i++) { ts += ss[i]; tc += cc2[i]; }
            out[0] = ts / tc;
            g_done = 0;   // reset for next graph replay
        }
    }
}

// ---------------------------------------------------------------------------
extern "C" void kernel_launch(void* const* d_in, const int* in_sizes, int n_in,
                              void* d_out, int out_size) {
    const float* emb = (const float*)d_in[0];
    const int* labels = (const int*)d_in[1];
    float* out = (float*)d_out;

    pd_fused<<<NBLK, 256>>>(emb);
    mine_final<<<MBLK, 128>>>(labels, out);
}